// round 9
// baseline (speedup 1.0000x reference)
#include <cuda_runtime.h>

#define SEQ    1024
#define BATCH  2048
#define HID    64
#define XCHUNK 256

typedef unsigned long long u64;

__device__ __forceinline__ u64 fma2(u64 a, u64 b, u64 c) {
    u64 d;
    asm("fma.rn.f32x2 %0, %1, %2, %3;" : "=l"(d) : "l"(a), "l"(b), "l"(c));
    return d;
}
__device__ __forceinline__ u64 add2(u64 a, u64 b) {
    u64 d;
    asm("add.rn.f32x2 %0, %1, %2;" : "=l"(d) : "l"(a), "l"(b));
    return d;
}
__device__ __forceinline__ u64 pack2(float a, float b) {
    u64 r;
    asm("mov.b64 %0, {%1, %2};" : "=l"(r) : "f"(a), "f"(b));
    return r;
}
__device__ __forceinline__ float2 unpack2(u64 v) {
    float2 f;
    asm("mov.b64 {%0, %1}, %2;" : "=f"(f.x), "=f"(f.y) : "l"(v));
    return f;
}
__device__ __forceinline__ float tanhA(float x) {
    float y;
    asm("tanh.approx.f32 %0, %1;" : "=f"(y) : "f"(x));
    return y;
}
__device__ __forceinline__ float sigA(float x) {
    return fmaf(0.5f, tanhA(0.5f * x), 0.5f);
}

// Layout: 256 threads per CTA, 1 batch element per CTA, 2 CTAs/SM.
//   lane group of 4: unit m = warp*8 + (lane>>2), q = lane&3.
//   Lane q computes gates {q, q^1} restricted to K-half kh = q&1
//   (2 gates x 32 weights = 32 packed f32x2 regs).
// Per step per thread: 8 LDS.128 of its h half, 32 FFMA2,
//   1 shfl to recombine K-halves, 1 MUFU activation (own gate),
//   3 shfl all-gather of i/f/g/o, redundant c/h update,
//   lane q==0 stores h. ONE __syncthreads per step (double-buffered h).
__global__ void __launch_bounds__(256, 2)
lstm_fused_kernel(const float* __restrict__ x,
                  const float* __restrict__ W_ih,
                  const float* __restrict__ W_hh,
                  const float* __restrict__ b_ih,
                  const float* __restrict__ b_hh,
                  const float* __restrict__ fc1_w,
                  const float* __restrict__ fc1_b,
                  const float* __restrict__ fc2_w,
                  const float* __restrict__ fc2_b,
                  float* __restrict__ out)
{
    const int b    = blockIdx.x;
    const int tid  = threadIdx.x;
    const int lane = tid & 31;
    const int q    = lane & 3;                          // gate owner 0..3
    const int m    = ((tid >> 5) << 3) + (lane >> 2);   // hidden unit 0..63
    const int kh   = q & 1;                             // K-half 0/1

    __shared__ __align__(16) float sh_h[2][HID];  // double-buffered hidden
    __shared__ float sh_x[XCHUNK];
    __shared__ float sh_c[HID];
    __shared__ float sh_hd[128];

    // ---- weights: gate q (row rA) and gate q^1 (row rB), K-half kh ----
    u64 wA[16], wB[16];
    const int rA = q * HID + m;
    const int rB = (q ^ 1) * HID + m;
    {
        const float4* pa = reinterpret_cast<const float4*>(W_hh + rA * HID + kh * 32);
        const float4* pb = reinterpret_cast<const float4*>(W_hh + rB * HID + kh * 32);
        #pragma unroll
        for (int i = 0; i < 8; i++) {
            float4 va = __ldg(pa + i);
            float4 vb = __ldg(pb + i);
            wA[2 * i]     = pack2(va.x, va.y);
            wA[2 * i + 1] = pack2(va.z, va.w);
            wB[2 * i]     = pack2(vb.x, vb.y);
            wB[2 * i + 1] = pack2(vb.z, vb.w);
        }
    }
    const float wih  = __ldg(W_ih + rA);                       // own gate only
    const float bias = __ldg(b_ih + rA) + __ldg(b_hh + rA);    // own gate only

    // ---- init ----
    if (tid < HID) sh_h[0][tid] = 0.0f;
    float c = 0.0f;   // replicated across the 4 lanes of each unit
    int   p = 0;

    // ---- time recurrence ----
    #pragma unroll 1
    for (int t0 = 0; t0 < SEQ; t0 += XCHUNK) {
        sh_x[tid] = __ldg(x + (t0 + tid) * BATCH + b);
        __syncthreads();   // covers x staging and prior-step h writes

        #pragma unroll 1
        for (int tt = 0; tt < XCHUNK; tt++) {
            const float xv = sh_x[tt];

            // partial dots over this lane's K-half, 2 gates
            const ulonglong2* h2 =
                reinterpret_cast<const ulonglong2*>(&sh_h[p][kh * 32]);
            u64 aA0 = 0ull, aA1 = 0ull, aB0 = 0ull, aB1 = 0ull;
            #pragma unroll
            for (int i = 0; i < 8; i++) {
                ulonglong2 hv = h2[i];      // 4 h values (1 LDS.128)
                aA0 = fma2(hv.x, wA[2 * i], aA0);
                aB0 = fma2(hv.x, wB[2 * i], aB0);
                aA1 = fma2(hv.y, wA[2 * i + 1], aA1);
                aB1 = fma2(hv.y, wB[2 * i + 1], aB1);
            }
            float2 fa = unpack2(add2(aA0, aA1));
            float2 fb = unpack2(add2(aB0, aB1));
            const float vA = fa.x + fa.y;     // own gate q, half kh
            const float vB = fb.x + fb.y;     // gate q^1,   half kh

            // recombine K-halves: lane q^1 holds gate q's other half in its vB
            const float otherHalf = __shfl_xor_sync(0xffffffffu, vB, 1);
            const float pre = vA + otherHalf + fmaf(xv, wih, bias);

            // activate own gate (gate 2 = tanh, others sigmoid)
            const float act = (q == 2) ? tanhA(pre) : sigA(pre);

            // all-gather 4 gates within the lane quad
            const float s1 = __shfl_xor_sync(0xffffffffu, act, 1);  // act(q^1)
            const float s2 = __shfl_xor_sync(0xffffffffu, act, 2);  // act(q^2)
            const float s3 = __shfl_xor_sync(0xffffffffu, s1, 2);   // act(q^3)

            // gate g lives in var index (q ^ g)
            const float iv = (q == 0) ? act : (q == 1) ? s1 : (q == 2) ? s2 : s3;
            const float fv = (q == 0) ? s1  : (q == 1) ? act : (q == 2) ? s3 : s2;
            const float gv = (q == 0) ? s2  : (q == 1) ? s3 : (q == 2) ? act : s1;
            const float ov = (q == 0) ? s3  : (q == 1) ? s2 : (q == 2) ? s1 : act;

            c = fmaf(fv, c, iv * gv);
            const float h = ov * tanhA(c);

            if (q == 0) sh_h[p ^ 1][m] = h;
            __syncthreads();
            p ^= 1;
        }
    }

    // ---- MLP head on cell state ----
    if (q == 0) sh_c[m] = c;
    __syncthreads();

    if (tid < 128) {
        const float* fw = fc1_w + tid * HID;
        float acc = __ldg(fc1_b + tid);
        #pragma unroll
        for (int k = 0; k < HID; k++) acc = fmaf(__ldg(fw + k), sh_c[k], acc);
        sh_hd[tid] = acc;
    }
    __syncthreads();

    if (tid < 5) {
        const float* fw = fc2_w + tid * 128;
        float acc = __ldg(fc2_b + tid);
        #pragma unroll
        for (int k = 0; k < 128; k++) acc = fmaf(__ldg(fw + k), sh_hd[k], acc);
        out[b * 5 + tid] = acc;
    }
}

extern "C" void kernel_launch(void* const* d_in, const int* in_sizes, int n_in,
                              void* d_out, int out_size)
{
    const float* x     = (const float*)d_in[0];
    const float* W_ih  = (const float*)d_in[1];
    const float* W_hh  = (const float*)d_in[2];
    const float* b_ih  = (const float*)d_in[3];
    const float* b_hh  = (const float*)d_in[4];
    const float* fc1_w = (const float*)d_in[5];
    const float* fc1_b = (const float*)d_in[6];
    const float* fc2_w = (const float*)d_in[7];
    const float* fc2_b = (const float*)d_in[8];
    float* out = (float*)d_out;

    lstm_fused_kernel<<<BATCH, 256>>>(x, W_ih, W_hh, b_ih, b_hh,
                                      fc1_w, fc1_b, fc2_w, fc2_b, out);
}

// round 10
// speedup vs baseline: 1.5145x; 1.5145x over previous
#include <cuda_runtime.h>

#define SEQ    1024
#define BATCH  2048
#define HID    64
#define G4     256
#define XCHUNK 256

typedef unsigned long long u64;

__device__ __forceinline__ u64 fma2(u64 a, u64 b, u64 c) {
    u64 d;
    asm("fma.rn.f32x2 %0, %1, %2, %3;" : "=l"(d) : "l"(a), "l"(b), "l"(c));
    return d;
}
__device__ __forceinline__ u64 add2(u64 a, u64 b) {
    u64 d;
    asm("add.rn.f32x2 %0, %1, %2;" : "=l"(d) : "l"(a), "l"(b));
    return d;
}
__device__ __forceinline__ u64 pack2(float a, float b) {
    u64 r;
    asm("mov.b64 %0, {%1, %2};" : "=l"(r) : "f"(a), "f"(b));
    return r;
}
__device__ __forceinline__ float2 unpack2(u64 v) {
    float2 f;
    asm("mov.b64 {%0, %1}, %2;" : "=f"(f.x), "=f"(f.y) : "l"(v));
    return f;
}
__device__ __forceinline__ float tanhA(float x) {
    float y;
    asm("tanh.approx.f32 %0, %1;" : "=f"(y) : "f"(x));
    return y;
}
__device__ __forceinline__ float sigA(float x) {
    return fmaf(0.5f, tanhA(0.5f * x), 0.5f);
}

// R4 layout + 2 batch elements per CTA (weights in regs reused for both).
// thread j = gate row (i:0-63, f:64-127, g:128-191, o:192-255).
// Per step: both dot products interleaved (8 FFMA2 chains), gates -> smem,
// barrier, threads 0-127 update (unit=j&63, batch=j>>6), barrier.
__global__ void __launch_bounds__(256, 2)
lstm_fused_kernel(const float* __restrict__ x,
                  const float* __restrict__ W_ih,
                  const float* __restrict__ W_hh,
                  const float* __restrict__ b_ih,
                  const float* __restrict__ b_hh,
                  const float* __restrict__ fc1_w,
                  const float* __restrict__ fc1_b,
                  const float* __restrict__ fc2_w,
                  const float* __restrict__ fc2_b,
                  float* __restrict__ out)
{
    const int b0 = blockIdx.x * 2;       // two batch columns per CTA
    const int j  = threadIdx.x;          // gate row 0..255

    __shared__ __align__(16) float sh_hA[HID];   // hidden state, batch 0
    __shared__ __align__(16) float sh_hB[HID];   // hidden state, batch 1
    __shared__ float sh_g[2][G4];                // activated gates per batch
    __shared__ float sh_x[2][XCHUNK];            // staged x columns
    __shared__ float sh_c[2][HID];
    __shared__ float sh_hd[2][128];

    // ---- W_hh row into registers as 32 packed f32x2 ----
    u64 w[32];
    {
        const float4* wr = reinterpret_cast<const float4*>(W_hh + j * HID);
        #pragma unroll
        for (int i = 0; i < 16; i++) {
            float4 v = __ldg(wr + i);
            w[2 * i]     = pack2(v.x, v.y);
            w[2 * i + 1] = pack2(v.z, v.w);
        }
    }
    const float wih  = __ldg(W_ih + j);
    const float bias = __ldg(b_ih + j) + __ldg(b_hh + j);

    // ---- init ----
    if (j < HID) { sh_hA[j] = 0.0f; sh_hB[j] = 0.0f; }
    float c_reg = 0.0f;     // valid for j < 128 (unit=j&63, batch=j>>6)
    __syncthreads();

    // ---- time recurrence ----
    #pragma unroll 1
    for (int t0 = 0; t0 < SEQ; t0 += XCHUNK) {
        sh_x[0][j] = __ldg(x + (t0 + j) * BATCH + b0);
        sh_x[1][j] = __ldg(x + (t0 + j) * BATCH + b0 + 1);
        __syncthreads();

        #pragma unroll 1
        for (int tt = 0; tt < XCHUNK; tt++) {
            const float xv0 = sh_x[0][tt];
            const float xv1 = sh_x[1][tt];

            // two dots, 8 independent packed acc chains
            const ulonglong2* hA = reinterpret_cast<const ulonglong2*>(sh_hA);
            const ulonglong2* hB = reinterpret_cast<const ulonglong2*>(sh_hB);
            u64 a0 = 0ull, a1 = 0ull, a2 = 0ull, a3 = 0ull;
            u64 e0 = 0ull, e1 = 0ull, e2 = 0ull, e3 = 0ull;
            #pragma unroll
            for (int i = 0; i < 16; i += 2) {
                ulonglong2 ha0 = hA[i];
                ulonglong2 hb0 = hB[i];
                ulonglong2 ha1 = hA[i + 1];
                ulonglong2 hb1 = hB[i + 1];
                a0 = fma2(ha0.x, w[2 * i],     a0);
                e0 = fma2(hb0.x, w[2 * i],     e0);
                a1 = fma2(ha0.y, w[2 * i + 1], a1);
                e1 = fma2(hb0.y, w[2 * i + 1], e1);
                a2 = fma2(ha1.x, w[2 * i + 2], a2);
                e2 = fma2(hb1.x, w[2 * i + 2], e2);
                a3 = fma2(ha1.y, w[2 * i + 3], a3);
                e3 = fma2(hb1.y, w[2 * i + 3], e3);
            }
            float2 sa = unpack2(add2(add2(a0, a2), add2(a1, a3)));
            float2 sb = unpack2(add2(add2(e0, e2), add2(e1, e3)));
            const float pre0 = fmaf(xv0, wih, bias) + (sa.x + sa.y);
            const float pre1 = fmaf(xv1, wih, bias) + (sb.x + sb.y);

            // activation (g-gate rows 128-191 = tanh, rest sigmoid)
            const bool is_g = (j >= 128 && j < 192);
            sh_g[0][j] = is_g ? tanhA(pre0) : sigA(pre0);
            sh_g[1][j] = is_g ? tanhA(pre1) : sigA(pre1);
            __syncthreads();

            if (j < 128) {                 // 4 warps update both batches
                const int u  = j & 63;
                const int bt = j >> 6;
                const float iv = sh_g[bt][u];
                const float fv = sh_g[bt][u + 64];
                const float gv = sh_g[bt][u + 128];
                const float ov = sh_g[bt][u + 192];
                c_reg = fmaf(fv, c_reg, iv * gv);
                const float h = ov * tanhA(c_reg);
                if (bt == 0) sh_hA[u] = h; else sh_hB[u] = h;
            }
            __syncthreads();
        }
    }

    // ---- MLP head on both cell states ----
    if (j < 128) sh_c[j >> 6][j & 63] = c_reg;
    __syncthreads();

    {   // fc1: 256 threads = 2 batches x 128 rows
        const int bt  = j >> 7;
        const int row = j & 127;
        const float* fw = fc1_w + row * HID;
        float acc = __ldg(fc1_b + row);
        #pragma unroll
        for (int k = 0; k < HID; k++) acc = fmaf(__ldg(fw + k), sh_c[bt][k], acc);
        sh_hd[bt][row] = acc;
    }
    __syncthreads();

    if (j < 10) {        // fc2: 2 batches x 5 rows
        const int bt  = j / 5;
        const int row = j % 5;
        const float* fw = fc2_w + row * 128;
        float acc = __ldg(fc2_b + row);
        #pragma unroll
        for (int k = 0; k < 128; k++) acc = fmaf(__ldg(fw + k), sh_hd[bt][k], acc);
        out[(b0 + bt) * 5 + row] = acc;
    }
}

extern "C" void kernel_launch(void* const* d_in, const int* in_sizes, int n_in,
                              void* d_out, int out_size)
{
    const float* x     = (const float*)d_in[0];
    const float* W_ih  = (const float*)d_in[1];
    const float* W_hh  = (const float*)d_in[2];
    const float* b_ih  = (const float*)d_in[3];
    const float* b_hh  = (const float*)d_in[4];
    const float* fc1_w = (const float*)d_in[5];
    const float* fc1_b = (const float*)d_in[6];
    const float* fc2_w = (const float*)d_in[7];
    const float* fc2_b = (const float*)d_in[8];
    float* out = (float*)d_out;

    lstm_fused_kernel<<<BATCH / 2, 256>>>(x, W_ih, W_hh, b_ih, b_hh,
                                          fc1_w, fc1_b, fc2_w, fc2_b, out);
}